// round 1
// baseline (speedup 1.0000x reference)
#include <cuda_runtime.h>
#include <math.h>

#define N 2048
#define IN_DIM 128
#define OUT_DIM 32
#define ROWS 4
#define NWARPS 8

// Scratch (allocation-free rule: __device__ globals)
__device__ float g_z[N * OUT_DIM];
__device__ float g_src[N];
__device__ float g_dst[N];
__device__ float g_R[OUT_DIM];
__device__ float g_phi[OUT_DIM];

// ---------------------------------------------------------------------------
// Prep: z = feat @ W ; src = z @ a[:32] ; dst = z @ a[32:64] ;
//       R_k, phi_k from (a[2k], a[2k+1]) so that
//       a[2k]*sin(t) + a[2k+1]*cos(t) == R_k * sin(t + phi_k)   (exact)
// ---------------------------------------------------------------------------
__global__ void prep_kernel(const float* __restrict__ feat,
                            const float* __restrict__ a,
                            const float* __restrict__ W) {
    int i = blockIdx.x;      // row
    int k = threadIdx.x;     // out dim, 32 threads = 1 warp
    float acc = 0.f;
#pragma unroll
    for (int d = 0; d < IN_DIM; ++d)
        acc = fmaf(feat[i * IN_DIM + d], W[d * OUT_DIM + k], acc);
    g_z[i * OUT_DIM + k] = acc;

    float s = acc * a[k];
    float t = acc * a[OUT_DIM + k];
#pragma unroll
    for (int o = 16; o > 0; o >>= 1) {
        s += __shfl_xor_sync(0xffffffffu, s, o);
        t += __shfl_xor_sync(0xffffffffu, t, o);
    }
    if (k == 0) { g_src[i] = s; g_dst[i] = t; }

    if (i == 0) {
        float ae = a[2 * k];
        float ao = a[2 * k + 1];
        g_R[k]   = sqrtf(ae * ae + ao * ao);
        g_phi[k] = atan2f(ao, ae);
    }
}

// ---------------------------------------------------------------------------
// Fused attention + softmax + att@z + residual + layernorm.
// One block = ROWS output rows. 8 warps stripe over j.
// Per (warp, j): lane k computes R_k*sin(dt*f_k + phi_k); butterfly-sum -> e.
// Masked (adj==0) pairs are skipped entirely (exact: exp(NEG_INF-max) == 0).
// Online softmax per warp with per-lane acc (one output dim per lane).
// ---------------------------------------------------------------------------
__global__ void __launch_bounds__(256)
attn_kernel(const int*   __restrict__ adj,
            const float* __restrict__ ts,
            const int*   __restrict__ time_end,
            const float* __restrict__ bf,
            const float* __restrict__ gamma,
            const float* __restrict__ beta,
            float*       __restrict__ out) {
    const int i0   = blockIdx.x * ROWS;
    const int warp = threadIdx.x >> 5;
    const int lane = threadIdx.x & 31;

    // time_end is an int scalar (hedge: if bits look like a float, reinterpret)
    int ti = *time_end;
    float T = (ti > -1000000 && ti < 1000000) ? (float)ti : __int_as_float(ti);

    const float f   = bf[lane];
    const float R   = g_R[lane];
    const float phi = g_phi[lane];

    float src[ROWS];
#pragma unroll
    for (int r = 0; r < ROWS; ++r) src[r] = g_src[i0 + r];

    float m[ROWS], l[ROWS], acc[ROWS];
#pragma unroll
    for (int r = 0; r < ROWS; ++r) { m[r] = -1e30f; l[r] = 0.f; acc[r] = 0.f; }

    for (int j = warp; j < N; j += NWARPS) {
        float zj   = g_z[j * OUT_DIM + lane];   // coalesced 128B
        float dstj = g_dst[j];                  // broadcast
        int amask[ROWS];
#pragma unroll
        for (int r = 0; r < ROWS; ++r) amask[r] = adj[(i0 + r) * N + j];

#pragma unroll
        for (int r = 0; r < ROWS; ++r) {
            if (amask[r] > 0) {                 // warp-uniform branch
                float dt    = T - ts[(i0 + r) * N + j];
                float theta = fmaf(dt, f, phi);
                float e     = R * __sinf(theta);
#pragma unroll
                for (int o = 16; o > 0; o >>= 1)
                    e += __shfl_xor_sync(0xffffffffu, e, o);
                e += src[r] + dstj;
                e = (e > 0.f) ? e : 0.05f * e;  // leaky relu
                if (e > m[r]) {                 // rare, warp-uniform
                    float c = __expf(m[r] - e);
                    l[r] *= c;  acc[r] *= c;  m[r] = e;
                }
                float p = __expf(e - m[r]);
                l[r] += p;
                acc[r] = fmaf(p, zj, acc[r]);
            }
        }
    }

    // Cross-warp combine
    __shared__ float sm_m[ROWS][NWARPS];
    __shared__ float sm_l[ROWS][NWARPS];
    __shared__ float sm_a[ROWS][NWARPS][OUT_DIM];
#pragma unroll
    for (int r = 0; r < ROWS; ++r) {
        if (lane == 0) { sm_m[r][warp] = m[r]; sm_l[r][warp] = l[r]; }
        sm_a[r][warp][lane] = acc[r];
    }
    __syncthreads();

    if (warp < ROWS) {
        const int r = warp;
        const int i = i0 + r;
        float M = -1e30f;
#pragma unroll
        for (int w = 0; w < NWARPS; ++w) M = fmaxf(M, sm_m[r][w]);
        float L = 0.f, A = 0.f;
#pragma unroll
        for (int w = 0; w < NWARPS; ++w) {
            float c = __expf(sm_m[r][w] - M);
            L += sm_l[r][w] * c;
            A  = fmaf(sm_a[r][w][lane], c, A);
        }
        float temp = A / L + g_z[i * OUT_DIM + lane];

        // LayerNorm over 32 dims (one warp)
        float mu = temp;
#pragma unroll
        for (int o = 16; o > 0; o >>= 1) mu += __shfl_xor_sync(0xffffffffu, mu, o);
        mu *= (1.0f / OUT_DIM);
        float d = temp - mu;
        float v = d * d;
#pragma unroll
        for (int o = 16; o > 0; o >>= 1) v += __shfl_xor_sync(0xffffffffu, v, o);
        v *= (1.0f / OUT_DIM);
        out[i * OUT_DIM + lane] = d * rsqrtf(v + 1e-6f) * gamma[lane] + beta[lane];
    }
}

// ---------------------------------------------------------------------------
extern "C" void kernel_launch(void* const* d_in, const int* in_sizes, int n_in,
                              void* d_out, int out_size) {
    const float* feat = (const float*)d_in[0];   // (2048,128) f32
    const int*   adj  = (const int*)  d_in[1];   // (2048,2048) i32
    const float* ts   = (const float*)d_in[2];   // (2048,2048) f32
    const float* a    = (const float*)d_in[3];   // (64,1) f32
    const int*   te   = (const int*)  d_in[4];   // scalar int
    const float* W    = (const float*)d_in[5];   // (128,32) f32
    const float* bf   = (const float*)d_in[6];   // (32,) f32
    const float* gam  = (const float*)d_in[7];   // (32,) f32
    const float* bet  = (const float*)d_in[8];   // (32,) f32
    float* out = (float*)d_out;                  // (2048,32) f32

    prep_kernel<<<N, 32>>>(feat, a, W);
    attn_kernel<<<N / ROWS, 256>>>(adj, ts, te, bf, gam, bet, out);
}